// round 9
// baseline (speedup 1.0000x reference)
#include <cuda_runtime.h>
#include <math.h>

#define NN 20000
#define NE 320000
#define NB 128
#define H  32
#define AF 64
#define BF 16
#define KP 1088
#define BM 144

typedef unsigned long long ull;

#define PK2(d, x, y)     asm("mov.b64 %0, {%1, %2};" : "=l"(d) : "f"(x), "f"(y))
#define UPK2(x, y, d)    asm("mov.b64 {%0, %1}, %2;" : "=f"(x), "=f"(y) : "l"(d))
#define FMA2(d, a, b, c) asm("fma.rn.f32x2 %0, %1, %2, %3;" : "=l"(d) : "l"(a), "l"(b), "l"(c))

__device__ float g_h[3][NN * H];
__device__ float g_t[NE * H];
__device__ float g_P[(long)NN * KP];
__device__ float g_m[NN * H];
__device__ float g_m2[NN * H];
__device__ float g_W2[KP * H];
__device__ float g_Wc[BF * H];
__device__ float g_bc[H];
__device__ float g_inv[NN];
__device__ int   g_deg[NN];
__device__ int   g_rp[NN + 1];
__device__ int   g_cur[NN];
__device__ int   g_eids[NE];

// -------- launch 1: hist + Wc collapse + h0 + W2 rearrange (all independent) --------
__global__ void __launch_bounds__(256) k_prep(
        const int* __restrict__ dst,
        const float* __restrict__ Wb, const float* __restrict__ bb,
        const float* __restrict__ We1, const float* __restrict__ be1,
        const float* __restrict__ nf, const float* __restrict__ Wa,
        const float* __restrict__ ba,
        const float* __restrict__ W_e2, const float* __restrict__ b_e2) {
    __shared__ float Ws[AF * H];
    __shared__ float bs[H];
    int b = blockIdx.x;
    int tid = threadIdx.x;
    if (b < 1250) {
        int e = b * 256 + tid;
        atomicAdd(&g_deg[dst[e]], 1);
    } else if (b == 1250) {
        #pragma unroll
        for (int r = 0; r < 2; r++) {
            int idx = tid + r * 256;
            int f = idx >> 5, o = idx & 31;
            float acc = 0.0f;
            #pragma unroll
            for (int j = 0; j < H; j++) acc += Wb[f * H + j] * We1[j * H + o];
            g_Wc[idx] = acc;
        }
        if (tid < H) {
            float acc = be1[tid];
            #pragma unroll
            for (int j = 0; j < H; j++) acc += bb[j] * We1[j * H + tid];
            g_bc[tid] = acc;
        }
    } else if (b < 3751) {
        // h0 = n_feat @ W_atom + b_atom, 4 accumulation chains
        for (int i = tid; i < AF * H; i += 256) Ws[i] = Wa[i];
        if (tid < H) bs[tid] = ba[tid];
        __syncthreads();
        int n = (b - 1251) * 8 + (tid >> 5);
        int c = tid & 31;
        const float4* r4 = (const float4*)(nf + n * AF);
        float a0 = bs[c], a1 = 0.0f, a2 = 0.0f, a3 = 0.0f;
        #pragma unroll
        for (int q = 0; q < 16; q++) {
            float4 v = __ldg(r4 + q);
            a0 += v.x * Ws[(4 * q + 0) * H + c];
            a1 += v.y * Ws[(4 * q + 1) * H + c];
            a2 += v.z * Ws[(4 * q + 2) * H + c];
            a3 += v.w * Ws[(4 * q + 3) * H + c];
        }
        g_h[0][n * H + c] = (a0 + a1) + (a2 + a3);
    } else {
        int idx = (b - 3751) * 256 + tid;
        int kk = idx >> 5, o = idx & 31;
        float v;
        if (kk < 1024)      v = W_e2[(kk >> 5) * 1024 + (kk & 31) * 32 + o];
        else if (kk < 1056) v = b_e2[(kk - 1024) * 32 + o];
        else                v = 0.0f;
        g_W2[idx] = v;
    }
}

// -------- launch 2: fast scan (each thread owns 20 elements) --------
__global__ void k_scan() {
    __shared__ int wsum[32];
    int t = threadIdx.x;            // 0..1023
    int lane = t & 31, w = t >> 5;
    bool act = t < 1000;
    int n0 = t * 20;
    int v[20];
    int s = 0;
    if (act) {
        #pragma unroll
        for (int j = 0; j < 20; j++) v[j] = g_deg[n0 + j];
        #pragma unroll
        for (int j = 0; j < 20; j++) s += v[j];
    }
    int incl = s;
    #pragma unroll
    for (int off = 1; off < 32; off <<= 1) {
        int tmp = __shfl_up_sync(0xffffffffu, incl, off);
        if (lane >= off) incl += tmp;
    }
    if (lane == 31) wsum[w] = incl;
    __syncthreads();
    if (w == 0) {
        int val = wsum[lane];
        int inc2 = val;
        #pragma unroll
        for (int off = 1; off < 32; off <<= 1) {
            int tmp = __shfl_up_sync(0xffffffffu, inc2, off);
            if (lane >= off) inc2 += tmp;
        }
        wsum[lane] = inc2 - val;    // exclusive warp offsets
    }
    __syncthreads();
    int excl = wsum[w] + incl - s;  // exclusive prefix for this thread
    if (act) {
        int run = excl;
        #pragma unroll
        for (int j = 0; j < 20; j++) {
            int i = n0 + j;
            g_rp[i]  = run;
            g_cur[i] = run;
            g_inv[i] = 1.0f / fmaxf((float)v[j], 1.0f);
            run += v[j];
        }
    }
    if (t == 1023) g_rp[NN] = excl;  // s==0 for inactive -> excl == total
}

// -------- launch 3: scatter (+deg re-zero) fused with t = relu(e_feat@Wc+bc) --------
__global__ void __launch_bounds__(256) k_scatter_t(const int* __restrict__ dst,
                                                   const float* __restrict__ ef) {
    int b = blockIdx.x;
    int tid = threadIdx.x;
    if (b < 1250) {
        int e = b * 256 + tid;
        int pos = atomicAdd(&g_cur[dst[e]], 1);
        g_eids[pos] = e;
        if (e < NN) g_deg[e] = 0;
    } else {
        int lane = tid & 31;
        float wcr[BF];
        #pragma unroll
        for (int f = 0; f < BF; f++) wcr[f] = g_Wc[f * H + lane];
        float bcv = g_bc[lane];
        int ebase = ((b - 1250) * 8 + (tid >> 5)) * 32;
        #pragma unroll 2
        for (int i = 0; i < 32; i += 2) {
            int ea = ebase + i, eb = ea + 1;
            const float4* ra = (const float4*)(ef + ea * BF);
            const float4* rb = (const float4*)(ef + eb * BF);
            float4 a0 = ra[0], a1 = ra[1], a2 = ra[2], a3 = ra[3];
            float4 c0 = rb[0], c1 = rb[1], c2 = rb[2], c3 = rb[3];
            float sa0 = bcv, sa1 = 0.0f, sb0 = bcv, sb1 = 0.0f;
            sa0 += a0.x * wcr[0]  + a0.z * wcr[2]  + a1.x * wcr[4]  + a1.z * wcr[6];
            sa1 += a0.y * wcr[1]  + a0.w * wcr[3]  + a1.y * wcr[5]  + a1.w * wcr[7];
            sa0 += a2.x * wcr[8]  + a2.z * wcr[10] + a3.x * wcr[12] + a3.z * wcr[14];
            sa1 += a2.y * wcr[9]  + a2.w * wcr[11] + a3.y * wcr[13] + a3.w * wcr[15];
            sb0 += c0.x * wcr[0]  + c0.z * wcr[2]  + c1.x * wcr[4]  + c1.z * wcr[6];
            sb1 += c0.y * wcr[1]  + c0.w * wcr[3]  + c1.y * wcr[5]  + c1.w * wcr[7];
            sb0 += c2.x * wcr[8]  + c2.z * wcr[10] + c3.x * wcr[12] + c3.z * wcr[14];
            sb1 += c2.y * wcr[9]  + c2.w * wcr[11] + c3.y * wcr[13] + c3.w * wcr[15];
            g_t[ea * H + lane] = fmaxf(sa0 + sa1, 0.0f);
            g_t[eb * H + lane] = fmaxf(sb0 + sb1, 0.0f);
        }
    }
}

// -------- launch 4 (PROFILED): per-dst outer product with integrated bucket sort --------
__device__ __forceinline__ void acc_edge(ull* acc2, const ull th2,
                                         const ulonglong2 t0, const ulonglong2 t1,
                                         const ulonglong2 t2, const ulonglong2 t3) {
    FMA2(acc2[0],  t0.x, th2, acc2[0]);
    FMA2(acc2[1],  t0.y, th2, acc2[1]);
    FMA2(acc2[2],  t1.x, th2, acc2[2]);
    FMA2(acc2[3],  t1.y, th2, acc2[3]);
    FMA2(acc2[4],  t2.x, th2, acc2[4]);
    FMA2(acc2[5],  t2.y, th2, acc2[5]);
    FMA2(acc2[6],  t3.x, th2, acc2[6]);
    FMA2(acc2[7],  t3.y, th2, acc2[7]);
}

__global__ void __launch_bounds__(256) k_accum(int hs, const int* __restrict__ src) {
    __shared__ int buf[8][128];
    const float* __restrict__ h = g_h[hs];
    int w = threadIdx.x >> 5;
    int d = blockIdx.x * 8 + w;
    int lane = threadIdx.x & 31;
    int beg = g_rp[d], end = g_rp[d + 1];
    int cnt = end - beg;
    if (cnt > 128) cnt = 128;  // impossible for this distribution; safety cap

    // sort bucket (ascending eid) into buf[w][0..cnt)
    if (cnt > 0 && cnt <= 32) {
        int e = (lane < cnt) ? __ldg(&g_eids[beg + lane]) : 0x7fffffff;
        int r = 0;
        #pragma unroll
        for (int j = 0; j < 32; j++) {
            int vj = __shfl_sync(0xffffffffu, e, j);
            r += (vj < e) ? 1 : 0;
        }
        if (lane < cnt) buf[w][r] = e;
        __syncwarp();
    } else if (cnt > 32) {
        for (int p = lane; p < cnt; p += 32) buf[w][p] = g_eids[beg + p];
        __syncwarp();
        for (int i = 0; i < cnt - 1; i++) {
            int bv = 0x7fffffff, bp = i;
            for (int p = i + lane; p < cnt; p += 32) {
                int vv = buf[w][p];
                if (vv < bv) { bv = vv; bp = p; }
            }
            #pragma unroll
            for (int off = 16; off; off >>= 1) {
                int ov = __shfl_down_sync(0xffffffffu, bv, off);
                int op = __shfl_down_sync(0xffffffffu, bp, off);
                if (ov < bv) { bv = ov; bp = op; }
            }
            bv = __shfl_sync(0xffffffffu, bv, 0);
            bp = __shfl_sync(0xffffffffu, bp, 0);
            if (lane == 0) { int tsw = buf[w][i]; buf[w][i] = bv; buf[w][bp] = tsw; }
            __syncwarp();
        }
    }

    ull acc2[16];
    #pragma unroll
    for (int q = 0; q < 16; q++) acc2[q] = 0ull;
    float hsum = 0.0f;
    for (int base = 0; base < cnt; base += 32) {
        int rem = cnt - base; if (rem > 32) rem = 32;
        int e_l = 0, s_l = 0;
        if (lane < rem) { e_l = buf[w][base + lane]; s_l = __ldg(&src[e_l]); }
        int p = 0;
        for (; p + 1 < rem; p += 2) {
            int e0 = __shfl_sync(0xffffffffu, e_l, p);
            int s0 = __shfl_sync(0xffffffffu, s_l, p);
            int e1 = __shfl_sync(0xffffffffu, e_l, p + 1);
            int s1 = __shfl_sync(0xffffffffu, s_l, p + 1);
            float hv0 = h[s0 * H + lane];
            float hv1 = h[s1 * H + lane];
            const ulonglong2* ta = (const ulonglong2*)(g_t + e0 * H);
            const ulonglong2* tb = (const ulonglong2*)(g_t + e1 * H);
            ulonglong2 a0 = ta[0], a1 = ta[1], a2 = ta[2], a3 = ta[3];
            ulonglong2 a4 = ta[4], a5 = ta[5], a6 = ta[6], a7 = ta[7];
            ulonglong2 b0 = tb[0], b1 = tb[1], b2 = tb[2], b3 = tb[3];
            ulonglong2 b4 = tb[4], b5 = tb[5], b6 = tb[6], b7 = tb[7];
            hsum += hv0;
            ull h20; PK2(h20, hv0, hv0);
            acc_edge(acc2,     h20, a0, a1, a2, a3);
            acc_edge(acc2 + 8, h20, a4, a5, a6, a7);
            hsum += hv1;
            ull h21; PK2(h21, hv1, hv1);
            acc_edge(acc2,     h21, b0, b1, b2, b3);
            acc_edge(acc2 + 8, h21, b4, b5, b6, b7);
        }
        if (p < rem) {
            int e0 = __shfl_sync(0xffffffffu, e_l, p);
            int s0 = __shfl_sync(0xffffffffu, s_l, p);
            float hv0 = h[s0 * H + lane];
            const ulonglong2* ta = (const ulonglong2*)(g_t + e0 * H);
            ulonglong2 a0 = ta[0], a1 = ta[1], a2 = ta[2], a3 = ta[3];
            ulonglong2 a4 = ta[4], a5 = ta[5], a6 = ta[6], a7 = ta[7];
            hsum += hv0;
            ull h20; PK2(h20, hv0, hv0);
            acc_edge(acc2,     h20, a0, a1, a2, a3);
            acc_edge(acc2 + 8, h20, a4, a5, a6, a7);
        }
    }
    float* Pr = g_P + (long)d * KP;
    #pragma unroll
    for (int q = 0; q < 16; q++) {
        float x, y; UPK2(x, y, acc2[q]);
        Pr[(2 * q) * H + lane]     = x;
        Pr[(2 * q + 1) * H + lane] = y;
    }
    Pr[1024 + lane] = hsum;
    Pr[1056 + lane] = 0.0f;
}

// -------- split-K GEMM (unchanged from R7) --------
__device__ __forceinline__ void gemm_load(int kb, int tid, int nb,
                                          float4* va, float4& wb0, float4& wb1) {
    #pragma unroll
    for (int i = 0; i < 8; i++) {
        int idx = i * 288 + tid;
        int node = idx >> 4, q = idx & 15;
        int gn = nb + node;
        if (gn < NN) va[i] = *(const float4*)(g_P + (long)gn * KP + kb + 4 * q);
        else         va[i] = make_float4(0.f, 0.f, 0.f, 0.f);
    }
    {
        int r = tid >> 3, c = (tid & 7) * 4;
        wb0 = *(const float4*)(g_W2 + (kb + r) * H + c);
    }
    if (tid < 224) {
        int idx = tid + 288;
        int r = idx >> 3, c = (idx & 7) * 4;
        wb1 = *(const float4*)(g_W2 + (kb + r) * H + c);
    }
}

__global__ void __launch_bounds__(288) k_gemm() {
    __shared__ float AsT[64][160];
    __shared__ float Bs[64][32];
    int tid = threadIdx.x;
    int nb = blockIdx.x * BM;
    int split = blockIdx.y;
    int t0 = split ? 9 : 0;
    int nt = split ? 8 : 9;
    float* mo = split ? g_m2 : g_m;
    int tx = tid & 7, ty = tid >> 3;
    ull acc[4][2];
    #pragma unroll
    for (int n = 0; n < 4; n++) { acc[n][0] = 0ull; acc[n][1] = 0ull; }

    float4 va[8];
    float4 wb0 = make_float4(0.f, 0.f, 0.f, 0.f), wb1 = wb0;
    gemm_load(t0 * 64, tid, nb, va, wb0, wb1);

    #pragma unroll 1
    for (int t = 0; t < nt; t++) {
        __syncthreads();
        #pragma unroll
        for (int i = 0; i < 8; i++) {
            int idx = i * 288 + tid;
            int node = idx >> 4, q = idx & 15;
            int col = node ^ ((q & 7) << 2);
            AsT[4 * q + 0][col] = va[i].x;
            AsT[4 * q + 1][col] = va[i].y;
            AsT[4 * q + 2][col] = va[i].z;
            AsT[4 * q + 3][col] = va[i].w;
        }
        { int r = tid >> 3, c = (tid & 7) * 4; *(float4*)&Bs[r][c] = wb0; }
        if (tid < 224) { int idx = tid + 288; int r = idx >> 3, c = (idx & 7) * 4; *(float4*)&Bs[r][c] = wb1; }
        __syncthreads();
        if (t + 1 < nt) gemm_load((t0 + t + 1) * 64, tid, nb, va, wb0, wb1);
        #pragma unroll 16
        for (int kk = 0; kk < 64; kk++) {
            float4 a4 = *(const float4*)&AsT[kk][(4 * ty) ^ (((kk >> 2) & 7) << 2)];
            ulonglong2 b2 = *(const ulonglong2*)&Bs[kk][4 * tx];
            ull aa;
            PK2(aa, a4.x, a4.x); FMA2(acc[0][0], aa, b2.x, acc[0][0]); FMA2(acc[0][1], aa, b2.y, acc[0][1]);
            PK2(aa, a4.y, a4.y); FMA2(acc[1][0], aa, b2.x, acc[1][0]); FMA2(acc[1][1], aa, b2.y, acc[1][1]);
            PK2(aa, a4.z, a4.z); FMA2(acc[2][0], aa, b2.x, acc[2][0]); FMA2(acc[2][1], aa, b2.y, acc[2][1]);
            PK2(aa, a4.w, a4.w); FMA2(acc[3][0], aa, b2.x, acc[3][0]); FMA2(acc[3][1], aa, b2.y, acc[3][1]);
        }
    }
    #pragma unroll
    for (int n = 0; n < 4; n++) {
        int node = nb + 4 * ty + n;
        if (node < NN) {
            float x0, x1, x2, x3;
            UPK2(x0, x1, acc[n][0]);
            UPK2(x2, x3, acc[n][1]);
            *(float4*)(mo + node * H + 4 * tx) = make_float4(x0, x1, x2, x3);
        }
    }
}

__global__ void k_gru(int hin, int hout,
                      const float* __restrict__ Wih, const float* __restrict__ Whh,
                      const float* __restrict__ bih, const float* __restrict__ bhh) {
    __shared__ float Wis[96 * 33], Whs[96 * 33];
    __shared__ float bis[96], bhs[96];
    for (int i = threadIdx.x; i < 96 * 32; i += 256) {
        int r = i >> 5, cc = i & 31;
        Wis[r * 33 + cc] = Wih[i];
        Whs[r * 33 + cc] = Whh[i];
    }
    if (threadIdx.x < 96) { bis[threadIdx.x] = bih[threadIdx.x]; bhs[threadIdx.x] = bhh[threadIdx.x]; }
    __syncthreads();
    int n = blockIdx.x * 8 + (threadIdx.x >> 5);
    int c = threadIdx.x & 31;
    float mv = fmaxf((g_m[n * H + c] + g_m2[n * H + c]) * g_inv[n], 0.0f);
    float hv = g_h[hin][n * H + c];
    float gi0 = bis[c], gi1 = bis[c + 32], gi2 = bis[c + 64];
    float gh0 = bhs[c], gh1 = bhs[c + 32], gh2 = bhs[c + 64];
    #pragma unroll
    for (int j = 0; j < H; j++) {
        float mj = __shfl_sync(0xffffffffu, mv, j);
        float hj = __shfl_sync(0xffffffffu, hv, j);
        gi0 += mj * Wis[c * 33 + j];
        gi1 += mj * Wis[(c + 32) * 33 + j];
        gi2 += mj * Wis[(c + 64) * 33 + j];
        gh0 += hj * Whs[c * 33 + j];
        gh1 += hj * Whs[(c + 32) * 33 + j];
        gh2 += hj * Whs[(c + 64) * 33 + j];
    }
    float r = 1.0f / (1.0f + __expf(-(gi0 + gh0)));
    float z = 1.0f / (1.0f + __expf(-(gi1 + gh1)));
    float nn = tanhf(gi2 + r * gh2);
    g_h[hout][n * H + c] = (1.0f - z) * nn + z * hv;
}

__device__ __forceinline__ int lbound(const int* a, int n, int key) {
    int lo = 0, hi = n;
    while (lo < hi) { int mid = (lo + hi) >> 1; if (a[mid] < key) lo = mid + 1; else hi = mid; }
    return lo;
}

__global__ void k_readout(int hs, const int* __restrict__ gid, float* __restrict__ out) {
    __shared__ float red[4][32];
    int b = blockIdx.x;
    int lo = lbound(gid, NN, b), hi = lbound(gid, NN, b + 1);
    int w = threadIdx.x >> 5, lane = threadIdx.x & 31;
    const float* h = g_h[hs];
    float s = 0.0f;
    for (int n = lo + w; n < hi; n += 4) s += h[n * H + lane];
    red[w][lane] = s;
    __syncthreads();
    if (w == 0) {
        float tot = red[0][lane] + red[1][lane] + red[2][lane] + red[3][lane];
        out[b * H + lane] = tot / fmaxf((float)(hi - lo), 1.0f);
    }
}

extern "C" void kernel_launch(void* const* d_in, const int* in_sizes, int n_in,
                              void* d_out, int out_size) {
    const float* n_feat = (const float*)d_in[0];
    const float* e_feat = (const float*)d_in[1];
    const int*   src    = (const int*)d_in[2];
    const int*   dst    = (const int*)d_in[3];
    const int*   gid    = (const int*)d_in[4];
    float* out = (float*)d_out;

    k_prep<<<3887, 256>>>(dst, (const float*)d_in[7], (const float*)d_in[8],
                          (const float*)d_in[9], (const float*)d_in[10],
                          n_feat, (const float*)d_in[5], (const float*)d_in[6],
                          (const float*)d_in[11], (const float*)d_in[12]);
    k_scan<<<1, 1024>>>();
    k_scatter_t<<<2500, 256>>>(dst, e_feat);

    dim3 ggrid((NN + BM - 1) / BM, 2);
    for (int l = 0; l < 2; l++) {
        k_accum<<<NN / 8, 256>>>(l, src);          // launch 4 on l==0 -> profiled
        k_gemm<<<ggrid, 288>>>();
        k_gru<<<NN / 8, 256>>>(l, l + 1, (const float*)d_in[13], (const float*)d_in[14],
                               (const float*)d_in[15], (const float*)d_in[16]);
    }
    k_readout<<<NB, 128>>>(2, gid, out);
}

// round 11
// speedup vs baseline: 1.0648x; 1.0648x over previous
#include <cuda_runtime.h>
#include <math.h>

#define NN 20000
#define NE 320000
#define NB 128
#define H  32
#define AF 64
#define BF 16
#define KP 1088
#define BM 144

typedef unsigned long long ull;

#define PK2(d, x, y)     asm("mov.b64 %0, {%1, %2};" : "=l"(d) : "f"(x), "f"(y))
#define UPK2(x, y, d)    asm("mov.b64 {%0, %1}, %2;" : "=f"(x), "=f"(y) : "l"(d))
#define FMA2(d, a, b, c) asm("fma.rn.f32x2 %0, %1, %2, %3;" : "=l"(d) : "l"(a), "l"(b), "l"(c))

__device__ float g_h[3][NN * H];
__device__ float g_t[NE * H];
__device__ float g_P[(long)NN * KP];
__device__ float g_m[NN * H];
__device__ float g_m2[NN * H];
__device__ float g_W2[KP * H];
__device__ float g_Wc[BF * H];
__device__ float g_bc[H];
__device__ float g_inv[NN];
__device__ int   g_deg[NN];
__device__ int   g_rp[NN + 1];
__device__ int   g_cur[NN];
__device__ int   g_eids[NE];

// -------- launch 1: hist + Wc collapse + h0 + W2 rearrange --------
__global__ void __launch_bounds__(256) k_prep(
        const int* __restrict__ dst,
        const float* __restrict__ Wb, const float* __restrict__ bb,
        const float* __restrict__ We1, const float* __restrict__ be1,
        const float* __restrict__ nf, const float* __restrict__ Wa,
        const float* __restrict__ ba,
        const float* __restrict__ W_e2, const float* __restrict__ b_e2) {
    __shared__ float Ws[AF * H];
    __shared__ float bs[H];
    int b = blockIdx.x;
    int tid = threadIdx.x;
    if (b < 1250) {
        int e = b * 256 + tid;
        atomicAdd(&g_deg[dst[e]], 1);
    } else if (b == 1250) {
        #pragma unroll
        for (int r = 0; r < 2; r++) {
            int idx = tid + r * 256;
            int f = idx >> 5, o = idx & 31;
            float acc = 0.0f;
            #pragma unroll
            for (int j = 0; j < H; j++) acc += Wb[f * H + j] * We1[j * H + o];
            g_Wc[idx] = acc;
        }
        if (tid < H) {
            float acc = be1[tid];
            #pragma unroll
            for (int j = 0; j < H; j++) acc += bb[j] * We1[j * H + tid];
            g_bc[tid] = acc;
        }
    } else if (b < 3751) {
        for (int i = tid; i < AF * H; i += 256) Ws[i] = Wa[i];
        if (tid < H) bs[tid] = ba[tid];
        __syncthreads();
        int n = (b - 1251) * 8 + (tid >> 5);
        int c = tid & 31;
        const float4* r4 = (const float4*)(nf + n * AF);
        float a0 = bs[c], a1 = 0.0f, a2 = 0.0f, a3 = 0.0f;
        #pragma unroll
        for (int q = 0; q < 16; q++) {
            float4 v = __ldg(r4 + q);
            a0 += v.x * Ws[(4 * q + 0) * H + c];
            a1 += v.y * Ws[(4 * q + 1) * H + c];
            a2 += v.z * Ws[(4 * q + 2) * H + c];
            a3 += v.w * Ws[(4 * q + 3) * H + c];
        }
        g_h[0][n * H + c] = (a0 + a1) + (a2 + a3);
    } else {
        int idx = (b - 3751) * 256 + tid;
        int kk = idx >> 5, o = idx & 31;
        float v;
        if (kk < 1024)      v = W_e2[(kk >> 5) * 1024 + (kk & 31) * 32 + o];
        else if (kk < 1056) v = b_e2[(kk - 1024) * 32 + o];
        else                v = 0.0f;
        g_W2[idx] = v;
    }
}

// -------- launch 2: fast scan --------
__global__ void k_scan() {
    __shared__ int wsum[32];
    int t = threadIdx.x;
    int lane = t & 31, w = t >> 5;
    bool act = t < 1000;
    int n0 = t * 20;
    int v[20];
    int s = 0;
    if (act) {
        #pragma unroll
        for (int j = 0; j < 20; j++) v[j] = g_deg[n0 + j];
        #pragma unroll
        for (int j = 0; j < 20; j++) s += v[j];
    }
    int incl = s;
    #pragma unroll
    for (int off = 1; off < 32; off <<= 1) {
        int tmp = __shfl_up_sync(0xffffffffu, incl, off);
        if (lane >= off) incl += tmp;
    }
    if (lane == 31) wsum[w] = incl;
    __syncthreads();
    if (w == 0) {
        int val = wsum[lane];
        int inc2 = val;
        #pragma unroll
        for (int off = 1; off < 32; off <<= 1) {
            int tmp = __shfl_up_sync(0xffffffffu, inc2, off);
            if (lane >= off) inc2 += tmp;
        }
        wsum[lane] = inc2 - val;
    }
    __syncthreads();
    int excl = wsum[w] + incl - s;
    if (act) {
        int run = excl;
        #pragma unroll
        for (int j = 0; j < 20; j++) {
            int i = n0 + j;
            g_rp[i]  = run;
            g_cur[i] = run;
            g_inv[i] = 1.0f / fmaxf((float)v[j], 1.0f);
            run += v[j];
        }
    }
    if (t == 1023) g_rp[NN] = excl;
}

// -------- launch 3: scatter + t --------
__global__ void __launch_bounds__(256) k_scatter_t(const int* __restrict__ dst,
                                                   const float* __restrict__ ef) {
    int b = blockIdx.x;
    int tid = threadIdx.x;
    if (b < 1250) {
        int e = b * 256 + tid;
        int pos = atomicAdd(&g_cur[dst[e]], 1);
        g_eids[pos] = e;
        if (e < NN) g_deg[e] = 0;
    } else {
        int lane = tid & 31;
        float wcr[BF];
        #pragma unroll
        for (int f = 0; f < BF; f++) wcr[f] = g_Wc[f * H + lane];
        float bcv = g_bc[lane];
        int ebase = ((b - 1250) * 8 + (tid >> 5)) * 32;
        #pragma unroll 2
        for (int i = 0; i < 32; i += 2) {
            int ea = ebase + i, eb = ea + 1;
            const float4* ra = (const float4*)(ef + ea * BF);
            const float4* rb = (const float4*)(ef + eb * BF);
            float4 a0 = ra[0], a1 = ra[1], a2 = ra[2], a3 = ra[3];
            float4 c0 = rb[0], c1 = rb[1], c2 = rb[2], c3 = rb[3];
            float sa0 = bcv, sa1 = 0.0f, sb0 = bcv, sb1 = 0.0f;
            sa0 += a0.x * wcr[0]  + a0.z * wcr[2]  + a1.x * wcr[4]  + a1.z * wcr[6];
            sa1 += a0.y * wcr[1]  + a0.w * wcr[3]  + a1.y * wcr[5]  + a1.w * wcr[7];
            sa0 += a2.x * wcr[8]  + a2.z * wcr[10] + a3.x * wcr[12] + a3.z * wcr[14];
            sa1 += a2.y * wcr[9]  + a2.w * wcr[11] + a3.y * wcr[13] + a3.w * wcr[15];
            sb0 += c0.x * wcr[0]  + c0.z * wcr[2]  + c1.x * wcr[4]  + c1.z * wcr[6];
            sb1 += c0.y * wcr[1]  + c0.w * wcr[3]  + c1.y * wcr[5]  + c1.w * wcr[7];
            sb0 += c2.x * wcr[8]  + c2.z * wcr[10] + c3.x * wcr[12] + c3.z * wcr[14];
            sb1 += c2.y * wcr[9]  + c2.w * wcr[11] + c3.y * wcr[13] + c3.w * wcr[15];
            g_t[ea * H + lane] = fmaxf(sa0 + sa1, 0.0f);
            g_t[eb * H + lane] = fmaxf(sb0 + sb1, 0.0f);
        }
    }
}

// -------- launch 4 (PROFILED): outer product; 2 warps per dst (k-split) --------
__global__ void __launch_bounds__(256, 4) k_accum(int hs, int do_sort,
                                                  const int* __restrict__ src) {
    __shared__ int buf[8][128];
    const float* __restrict__ h = g_h[hs];
    int w = threadIdx.x >> 5;
    int pair = w >> 1;           // dst slot within block (0..3)
    int half = w & 1;            // k-half: [16*half, 16*half+16)
    int d = blockIdx.x * 4 + pair;
    int lane = threadIdx.x & 31;
    int beg = g_rp[d], end = g_rp[d + 1];
    int cnt = end - beg;
    if (cnt > 128) cnt = 128;

    if (do_sort) {
        if (cnt > 0 && cnt <= 32) {
            int e = (lane < cnt) ? g_eids[beg + lane] : 0x7fffffff;
            int r = 0;
            #pragma unroll
            for (int j = 0; j < 32; j++) {
                int vj = __shfl_sync(0xffffffffu, e, j);
                r += (vj < e) ? 1 : 0;
            }
            if (lane < cnt) buf[w][r] = e;
            __syncwarp();
        } else if (cnt > 32) {
            for (int p = lane; p < cnt; p += 32) buf[w][p] = g_eids[beg + p];
            __syncwarp();
            for (int i = 0; i < cnt - 1; i++) {
                int bv = 0x7fffffff, bp = i;
                for (int p = i + lane; p < cnt; p += 32) {
                    int vv = buf[w][p];
                    if (vv < bv) { bv = vv; bp = p; }
                }
                #pragma unroll
                for (int off = 16; off; off >>= 1) {
                    int ov = __shfl_down_sync(0xffffffffu, bv, off);
                    int op = __shfl_down_sync(0xffffffffu, bp, off);
                    if (ov < bv) { bv = ov; bp = op; }
                }
                bv = __shfl_sync(0xffffffffu, bv, 0);
                bp = __shfl_sync(0xffffffffu, bp, 0);
                if (lane == 0) { int tsw = buf[w][i]; buf[w][i] = bv; buf[w][bp] = tsw; }
                __syncwarp();
            }
        }
        // both pair-warps finished reading g_eids -> half0 may write back sorted order
        asm volatile("bar.sync %0, 64;" :: "r"(pair + 1) : "memory");
        if (half == 0) {
            for (int p = lane; p < cnt; p += 32) g_eids[beg + p] = buf[w][p];
        }
    }

    ull acc2[8];
    #pragma unroll
    for (int q = 0; q < 8; q++) acc2[q] = 0ull;
    float hsum = 0.0f;
    int toff = half << 4;   // element offset into t row

    for (int base = 0; base < cnt; base += 32) {
        int rem = cnt - base; if (rem > 32) rem = 32;
        int e_l = 0, s_l = 0;
        if (lane < rem) {
            e_l = do_sort ? buf[w][base + lane] : __ldg(&g_eids[beg + base + lane]);
            s_l = __ldg(&src[e_l]);
        }
        int p = 0;
        for (; p + 1 < rem; p += 2) {
            int e0 = __shfl_sync(0xffffffffu, e_l, p);
            int s0 = __shfl_sync(0xffffffffu, s_l, p);
            int e1 = __shfl_sync(0xffffffffu, e_l, p + 1);
            int s1 = __shfl_sync(0xffffffffu, s_l, p + 1);
            float hv0 = h[s0 * H + lane];
            float hv1 = h[s1 * H + lane];
            const ulonglong2* ta = (const ulonglong2*)(g_t + e0 * H + toff);
            const ulonglong2* tb = (const ulonglong2*)(g_t + e1 * H + toff);
            ulonglong2 a0 = ta[0], a1 = ta[1], a2 = ta[2], a3 = ta[3];
            ulonglong2 b0 = tb[0], b1 = tb[1], b2 = tb[2], b3 = tb[3];
            hsum += hv0;
            ull h20; PK2(h20, hv0, hv0);
            FMA2(acc2[0], a0.x, h20, acc2[0]);
            FMA2(acc2[1], a0.y, h20, acc2[1]);
            FMA2(acc2[2], a1.x, h20, acc2[2]);
            FMA2(acc2[3], a1.y, h20, acc2[3]);
            FMA2(acc2[4], a2.x, h20, acc2[4]);
            FMA2(acc2[5], a2.y, h20, acc2[5]);
            FMA2(acc2[6], a3.x, h20, acc2[6]);
            FMA2(acc2[7], a3.y, h20, acc2[7]);
            hsum += hv1;
            ull h21; PK2(h21, hv1, hv1);
            FMA2(acc2[0], b0.x, h21, acc2[0]);
            FMA2(acc2[1], b0.y, h21, acc2[1]);
            FMA2(acc2[2], b1.x, h21, acc2[2]);
            FMA2(acc2[3], b1.y, h21, acc2[3]);
            FMA2(acc2[4], b2.x, h21, acc2[4]);
            FMA2(acc2[5], b2.y, h21, acc2[5]);
            FMA2(acc2[6], b3.x, h21, acc2[6]);
            FMA2(acc2[7], b3.y, h21, acc2[7]);
        }
        if (p < rem) {
            int e0 = __shfl_sync(0xffffffffu, e_l, p);
            int s0 = __shfl_sync(0xffffffffu, s_l, p);
            float hv0 = h[s0 * H + lane];
            const ulonglong2* ta = (const ulonglong2*)(g_t + e0 * H + toff);
            ulonglong2 a0 = ta[0], a1 = ta[1], a2 = ta[2], a3 = ta[3];
            hsum += hv0;
            ull h20; PK2(h20, hv0, hv0);
            FMA2(acc2[0], a0.x, h20, acc2[0]);
            FMA2(acc2[1], a0.y, h20, acc2[1]);
            FMA2(acc2[2], a1.x, h20, acc2[2]);
            FMA2(acc2[3], a1.y, h20, acc2[3]);
            FMA2(acc2[4], a2.x, h20, acc2[4]);
            FMA2(acc2[5], a2.y, h20, acc2[5]);
            FMA2(acc2[6], a3.x, h20, acc2[6]);
            FMA2(acc2[7], a3.y, h20, acc2[7]);
        }
    }
    float* Pr = g_P + (long)d * KP;
    #pragma unroll
    for (int q = 0; q < 8; q++) {
        float x, y; UPK2(x, y, acc2[q]);
        Pr[(toff + 2 * q) * H + lane]     = x;
        Pr[(toff + 2 * q + 1) * H + lane] = y;
    }
    if (half == 0) Pr[1024 + lane] = hsum;
    else           Pr[1056 + lane] = 0.0f;
}

// -------- split-K GEMM --------
__device__ __forceinline__ void gemm_load(int kb, int tid, int nb,
                                          float4* va, float4& wb0, float4& wb1) {
    #pragma unroll
    for (int i = 0; i < 8; i++) {
        int idx = i * 288 + tid;
        int node = idx >> 4, q = idx & 15;
        int gn = nb + node;
        if (gn < NN) va[i] = *(const float4*)(g_P + (long)gn * KP + kb + 4 * q);
        else         va[i] = make_float4(0.f, 0.f, 0.f, 0.f);
    }
    {
        int r = tid >> 3, c = (tid & 7) * 4;
        wb0 = *(const float4*)(g_W2 + (kb + r) * H + c);
    }
    if (tid < 224) {
        int idx = tid + 288;
        int r = idx >> 3, c = (idx & 7) * 4;
        wb1 = *(const float4*)(g_W2 + (kb + r) * H + c);
    }
}

__global__ void __launch_bounds__(288) k_gemm() {
    __shared__ float AsT[64][160];
    __shared__ float Bs[64][32];
    int tid = threadIdx.x;
    int nb = blockIdx.x * BM;
    int split = blockIdx.y;
    int t0 = split ? 9 : 0;
    int nt = split ? 8 : 9;
    float* mo = split ? g_m2 : g_m;
    int tx = tid & 7, ty = tid >> 3;
    ull acc[4][2];
    #pragma unroll
    for (int n = 0; n < 4; n++) { acc[n][0] = 0ull; acc[n][1] = 0ull; }

    float4 va[8];
    float4 wb0 = make_float4(0.f, 0.f, 0.f, 0.f), wb1 = wb0;
    gemm_load(t0 * 64, tid, nb, va, wb0, wb1);

    #pragma unroll 1
    for (int t = 0; t < nt; t++) {
        __syncthreads();
        #pragma unroll
        for (int i = 0; i < 8; i++) {
            int idx = i * 288 + tid;
            int node = idx >> 4, q = idx & 15;
            int col = node ^ ((q & 7) << 2);
            AsT[4 * q + 0][col] = va[i].x;
            AsT[4 * q + 1][col] = va[i].y;
            AsT[4 * q + 2][col] = va[i].z;
            AsT[4 * q + 3][col] = va[i].w;
        }
        { int r = tid >> 3, c = (tid & 7) * 4; *(float4*)&Bs[r][c] = wb0; }
        if (tid < 224) { int idx = tid + 288; int r = idx >> 3, c = (idx & 7) * 4; *(float4*)&Bs[r][c] = wb1; }
        __syncthreads();
        if (t + 1 < nt) gemm_load((t0 + t + 1) * 64, tid, nb, va, wb0, wb1);
        #pragma unroll 16
        for (int kk = 0; kk < 64; kk++) {
            float4 a4 = *(const float4*)&AsT[kk][(4 * ty) ^ (((kk >> 2) & 7) << 2)];
            ulonglong2 b2 = *(const ulonglong2*)&Bs[kk][4 * tx];
            ull aa;
            PK2(aa, a4.x, a4.x); FMA2(acc[0][0], aa, b2.x, acc[0][0]); FMA2(acc[0][1], aa, b2.y, acc[0][1]);
            PK2(aa, a4.y, a4.y); FMA2(acc[1][0], aa, b2.x, acc[1][0]); FMA2(acc[1][1], aa, b2.y, acc[1][1]);
            PK2(aa, a4.z, a4.z); FMA2(acc[2][0], aa, b2.x, acc[2][0]); FMA2(acc[2][1], aa, b2.y, acc[2][1]);
            PK2(aa, a4.w, a4.w); FMA2(acc[3][0], aa, b2.x, acc[3][0]); FMA2(acc[3][1], aa, b2.y, acc[3][1]);
        }
    }
    #pragma unroll
    for (int n = 0; n < 4; n++) {
        int node = nb + 4 * ty + n;
        if (node < NN) {
            float x0, x1, x2, x3;
            UPK2(x0, x1, acc[n][0]);
            UPK2(x2, x3, acc[n][1]);
            *(float4*)(mo + node * H + 4 * tx) = make_float4(x0, x1, x2, x3);
        }
    }
}

__global__ void k_gru(int hin, int hout,
                      const float* __restrict__ Wih, const float* __restrict__ Whh,
                      const float* __restrict__ bih, const float* __restrict__ bhh) {
    __shared__ float Wis[96 * 33], Whs[96 * 33];
    __shared__ float bis[96], bhs[96];
    for (int i = threadIdx.x; i < 96 * 32; i += 256) {
        int r = i >> 5, cc = i & 31;
        Wis[r * 33 + cc] = Wih[i];
        Whs[r * 33 + cc] = Whh[i];
    }
    if (threadIdx.x < 96) { bis[threadIdx.x] = bih[threadIdx.x]; bhs[threadIdx.x] = bhh[threadIdx.x]; }
    __syncthreads();
    int n = blockIdx.x * 8 + (threadIdx.x >> 5);
    int c = threadIdx.x & 31;
    float mv = fmaxf((g_m[n * H + c] + g_m2[n * H + c]) * g_inv[n], 0.0f);
    float hv = g_h[hin][n * H + c];
    float gi0 = bis[c], gi1 = bis[c + 32], gi2 = bis[c + 64];
    float gh0 = bhs[c], gh1 = bhs[c + 32], gh2 = bhs[c + 64];
    #pragma unroll
    for (int j = 0; j < H; j++) {
        float mj = __shfl_sync(0xffffffffu, mv, j);
        float hj = __shfl_sync(0xffffffffu, hv, j);
        gi0 += mj * Wis[c * 33 + j];
        gi1 += mj * Wis[(c + 32) * 33 + j];
        gi2 += mj * Wis[(c + 64) * 33 + j];
        gh0 += hj * Whs[c * 33 + j];
        gh1 += hj * Whs[(c + 32) * 33 + j];
        gh2 += hj * Whs[(c + 64) * 33 + j];
    }
    float r = 1.0f / (1.0f + __expf(-(gi0 + gh0)));
    float z = 1.0f / (1.0f + __expf(-(gi1 + gh1)));
    float nn = tanhf(gi2 + r * gh2);
    g_h[hout][n * H + c] = (1.0f - z) * nn + z * hv;
}

__device__ __forceinline__ int lbound(const int* a, int n, int key) {
    int lo = 0, hi = n;
    while (lo < hi) { int mid = (lo + hi) >> 1; if (a[mid] < key) lo = mid + 1; else hi = mid; }
    return lo;
}

__global__ void k_readout(int hs, const int* __restrict__ gid, float* __restrict__ out) {
    __shared__ float red[4][32];
    int b = blockIdx.x;
    int lo = lbound(gid, NN, b), hi = lbound(gid, NN, b + 1);
    int w = threadIdx.x >> 5, lane = threadIdx.x & 31;
    const float* h = g_h[hs];
    float s = 0.0f;
    for (int n = lo + w; n < hi; n += 4) s += h[n * H + lane];
    red[w][lane] = s;
    __syncthreads();
    if (w == 0) {
        float tot = red[0][lane] + red[1][lane] + red[2][lane] + red[3][lane];
        out[b * H + lane] = tot / fmaxf((float)(hi - lo), 1.0f);
    }
}

extern "C" void kernel_launch(void* const* d_in, const int* in_sizes, int n_in,
                              void* d_out, int out_size) {
    const float* n_feat = (const float*)d_in[0];
    const float* e_feat = (const float*)d_in[1];
    const int*   src    = (const int*)d_in[2];
    const int*   dst    = (const int*)d_in[3];
    const int*   gid    = (const int*)d_in[4];
    float* out = (float*)d_out;

    k_prep<<<3887, 256>>>(dst, (const float*)d_in[7], (const float*)d_in[8],
                          (const float*)d_in[9], (const float*)d_in[10],
                          n_feat, (const float*)d_in[5], (const float*)d_in[6],
                          (const float*)d_in[11], (const float*)d_in[12]);
    k_scan<<<1, 1024>>>();
    k_scatter_t<<<2500, 256>>>(dst, e_feat);

    dim3 ggrid((NN + BM - 1) / BM, 2);
    for (int l = 0; l < 2; l++) {
        k_accum<<<NN / 4, 256>>>(l, l == 0 ? 1 : 0, src);   // 4th launch on l==0 -> profiled
        k_gemm<<<ggrid, 288>>>();
        k_gru<<<NN / 8, 256>>>(l, l + 1, (const float*)d_in[13], (const float*)d_in[14],
                               (const float*)d_in[15], (const float*)d_in[16]);
    }
    k_readout<<<NB, 128>>>(2, gid, out);
}

// round 12
// speedup vs baseline: 1.1362x; 1.0671x over previous
#include <cuda_runtime.h>
#include <math.h>

#define NN 20000
#define NE 320000
#define NB 128
#define H  32
#define AF 64
#define BF 16
#define KP 1088
#define BM 144

typedef unsigned long long ull;

#define PK2(d, x, y)     asm("mov.b64 %0, {%1, %2};" : "=l"(d) : "f"(x), "f"(y))
#define UPK2(x, y, d)    asm("mov.b64 {%0, %1}, %2;" : "=f"(x), "=f"(y) : "l"(d))
#define FMA2(d, a, b, c) asm("fma.rn.f32x2 %0, %1, %2, %3;" : "=l"(d) : "l"(a), "l"(b), "l"(c))

__device__ float g_h[3][NN * H];
__device__ float g_t[NE * H];
__device__ float g_P[(long)NN * KP];
__device__ float g_m[NN * H];
__device__ float g_m2[NN * H];
__device__ float g_W2[KP * H];
__device__ float g_Wc[BF * H];
__device__ float g_bc[H];
__device__ float g_inv[NN];
__device__ int   g_deg[NN];
__device__ int   g_rp[NN + 1];
__device__ int   g_cur[NN];
__device__ int   g_eids[NE];

// -------- launch 1: hist + Wc collapse + h0 + W2 rearrange --------
__global__ void __launch_bounds__(256) k_prep(
        const int* __restrict__ dst,
        const float* __restrict__ Wb, const float* __restrict__ bb,
        const float* __restrict__ We1, const float* __restrict__ be1,
        const float* __restrict__ nf, const float* __restrict__ Wa,
        const float* __restrict__ ba,
        const float* __restrict__ W_e2, const float* __restrict__ b_e2) {
    __shared__ float Ws[AF * H];
    __shared__ float bs[H];
    int b = blockIdx.x;
    int tid = threadIdx.x;
    if (b < 1250) {
        int e = b * 256 + tid;
        atomicAdd(&g_deg[dst[e]], 1);
    } else if (b == 1250) {
        #pragma unroll
        for (int r = 0; r < 2; r++) {
            int idx = tid + r * 256;
            int f = idx >> 5, o = idx & 31;
            float acc = 0.0f;
            #pragma unroll
            for (int j = 0; j < H; j++) acc += Wb[f * H + j] * We1[j * H + o];
            g_Wc[idx] = acc;
        }
        if (tid < H) {
            float acc = be1[tid];
            #pragma unroll
            for (int j = 0; j < H; j++) acc += bb[j] * We1[j * H + tid];
            g_bc[tid] = acc;
        }
    } else if (b < 3751) {
        for (int i = tid; i < AF * H; i += 256) Ws[i] = Wa[i];
        if (tid < H) bs[tid] = ba[tid];
        __syncthreads();
        int n = (b - 1251) * 8 + (tid >> 5);
        int c = tid & 31;
        const float4* r4 = (const float4*)(nf + n * AF);
        float a0 = bs[c], a1 = 0.0f, a2 = 0.0f, a3 = 0.0f;
        #pragma unroll
        for (int q = 0; q < 16; q++) {
            float4 v = __ldg(r4 + q);
            a0 += v.x * Ws[(4 * q + 0) * H + c];
            a1 += v.y * Ws[(4 * q + 1) * H + c];
            a2 += v.z * Ws[(4 * q + 2) * H + c];
            a3 += v.w * Ws[(4 * q + 3) * H + c];
        }
        g_h[0][n * H + c] = (a0 + a1) + (a2 + a3);
    } else {
        int idx = (b - 3751) * 256 + tid;
        int kk = idx >> 5, o = idx & 31;
        float v;
        if (kk < 1024)      v = W_e2[(kk >> 5) * 1024 + (kk & 31) * 32 + o];
        else if (kk < 1056) v = b_e2[(kk - 1024) * 32 + o];
        else                v = 0.0f;
        g_W2[idx] = v;
    }
}

// -------- launch 2: fast scan --------
__global__ void k_scan() {
    __shared__ int wsum[32];
    int t = threadIdx.x;
    int lane = t & 31, w = t >> 5;
    bool act = t < 1000;
    int n0 = t * 20;
    int v[20];
    int s = 0;
    if (act) {
        #pragma unroll
        for (int j = 0; j < 20; j++) v[j] = g_deg[n0 + j];
        #pragma unroll
        for (int j = 0; j < 20; j++) s += v[j];
    }
    int incl = s;
    #pragma unroll
    for (int off = 1; off < 32; off <<= 1) {
        int tmp = __shfl_up_sync(0xffffffffu, incl, off);
        if (lane >= off) incl += tmp;
    }
    if (lane == 31) wsum[w] = incl;
    __syncthreads();
    if (w == 0) {
        int val = wsum[lane];
        int inc2 = val;
        #pragma unroll
        for (int off = 1; off < 32; off <<= 1) {
            int tmp = __shfl_up_sync(0xffffffffu, inc2, off);
            if (lane >= off) inc2 += tmp;
        }
        wsum[lane] = inc2 - val;
    }
    __syncthreads();
    int excl = wsum[w] + incl - s;
    if (act) {
        int run = excl;
        #pragma unroll
        for (int j = 0; j < 20; j++) {
            int i = n0 + j;
            g_rp[i]  = run;
            g_cur[i] = run;
            g_inv[i] = 1.0f / fmaxf((float)v[j], 1.0f);
            run += v[j];
        }
    }
    if (t == 1023) g_rp[NN] = excl;
}

// -------- launch 3: scatter + t --------
__global__ void __launch_bounds__(256) k_scatter_t(const int* __restrict__ dst,
                                                   const float* __restrict__ ef) {
    int b = blockIdx.x;
    int tid = threadIdx.x;
    if (b < 1250) {
        int e = b * 256 + tid;
        int pos = atomicAdd(&g_cur[dst[e]], 1);
        g_eids[pos] = e;
        if (e < NN) g_deg[e] = 0;
    } else {
        int lane = tid & 31;
        float wcr[BF];
        #pragma unroll
        for (int f = 0; f < BF; f++) wcr[f] = g_Wc[f * H + lane];
        float bcv = g_bc[lane];
        int ebase = ((b - 1250) * 8 + (tid >> 5)) * 32;
        #pragma unroll 2
        for (int i = 0; i < 32; i += 2) {
            int ea = ebase + i, eb = ea + 1;
            const float4* ra = (const float4*)(ef + ea * BF);
            const float4* rb = (const float4*)(ef + eb * BF);
            float4 a0 = ra[0], a1 = ra[1], a2 = ra[2], a3 = ra[3];
            float4 c0 = rb[0], c1 = rb[1], c2 = rb[2], c3 = rb[3];
            float sa0 = bcv, sa1 = 0.0f, sb0 = bcv, sb1 = 0.0f;
            sa0 += a0.x * wcr[0]  + a0.z * wcr[2]  + a1.x * wcr[4]  + a1.z * wcr[6];
            sa1 += a0.y * wcr[1]  + a0.w * wcr[3]  + a1.y * wcr[5]  + a1.w * wcr[7];
            sa0 += a2.x * wcr[8]  + a2.z * wcr[10] + a3.x * wcr[12] + a3.z * wcr[14];
            sa1 += a2.y * wcr[9]  + a2.w * wcr[11] + a3.y * wcr[13] + a3.w * wcr[15];
            sb0 += c0.x * wcr[0]  + c0.z * wcr[2]  + c1.x * wcr[4]  + c1.z * wcr[6];
            sb1 += c0.y * wcr[1]  + c0.w * wcr[3]  + c1.y * wcr[5]  + c1.w * wcr[7];
            sb0 += c2.x * wcr[8]  + c2.z * wcr[10] + c3.x * wcr[12] + c3.z * wcr[14];
            sb1 += c2.y * wcr[9]  + c2.w * wcr[11] + c3.y * wcr[13] + c3.w * wcr[15];
            g_t[ea * H + lane] = fmaxf(sa0 + sa1, 0.0f);
            g_t[eb * H + lane] = fmaxf(sb0 + sb1, 0.0f);
        }
    }
}

// -------- launch 4 (PROFILED): outer product; 2 warps/dst, smem-staged batches --------
__global__ void __launch_bounds__(256, 4) k_accum(int hs, int do_sort,
                                                  const int* __restrict__ src) {
    __shared__ int   sbuf[4][128];
    __shared__ float t_st[4][32][36];   // full t rows, pitch 36 (bank-conflict-free)
    __shared__ float h_st[4][32][36];   // gathered h rows
    const float* __restrict__ h = g_h[hs];
    int w = threadIdx.x >> 5;
    int pair = w >> 1;            // dst slot in block (0..3)
    int half = w & 1;             // k-half
    int d = blockIdx.x * 4 + pair;
    int lane = threadIdx.x & 31;
    int beg = g_rp[d], end = g_rp[d + 1];
    int cnt = end - beg;
    if (cnt > 128) cnt = 128;

    if (do_sort) {
        if (half == 0) {
            if (cnt > 0 && cnt <= 32) {
                int e = (lane < cnt) ? g_eids[beg + lane] : 0x7fffffff;
                int r = 0;
                #pragma unroll
                for (int j = 0; j < 32; j++) {
                    int vj = __shfl_sync(0xffffffffu, e, j);
                    r += (vj < e) ? 1 : 0;
                }
                if (lane < cnt) sbuf[pair][r] = e;
                __syncwarp();
                if (lane < cnt) g_eids[beg + lane] = sbuf[pair][lane];
            } else if (cnt > 32) {
                for (int p = lane; p < cnt; p += 32) sbuf[pair][p] = g_eids[beg + p];
                __syncwarp();
                for (int i = 0; i < cnt - 1; i++) {
                    int bv = 0x7fffffff, bp = i;
                    for (int p = i + lane; p < cnt; p += 32) {
                        int vv = sbuf[pair][p];
                        if (vv < bv) { bv = vv; bp = p; }
                    }
                    #pragma unroll
                    for (int off = 16; off; off >>= 1) {
                        int ov = __shfl_down_sync(0xffffffffu, bv, off);
                        int op = __shfl_down_sync(0xffffffffu, bp, off);
                        if (ov < bv) { bv = ov; bp = op; }
                    }
                    bv = __shfl_sync(0xffffffffu, bv, 0);
                    bp = __shfl_sync(0xffffffffu, bp, 0);
                    if (lane == 0) { int tsw = sbuf[pair][i]; sbuf[pair][i] = bv; sbuf[pair][bp] = tsw; }
                    __syncwarp();
                }
                for (int p = lane; p < cnt; p += 32) g_eids[beg + p] = sbuf[pair][p];
            }
        }
        asm volatile("bar.sync %0, 64;" :: "r"(pair + 1) : "memory");
    }

    ull acc2[8];
    #pragma unroll
    for (int q = 0; q < 8; q++) acc2[q] = 0ull;
    float hsum = 0.0f;
    int toff = half << 4;

    for (int base = 0; base < cnt; base += 32) {
        int rem = cnt - base; if (rem > 32) rem = 32;
        int e_l = 0, s_l = 0;
        if (lane < rem) {
            e_l = g_eids[beg + base + lane];       // plain load (g_eids written this kernel)
            s_l = __ldg(&src[e_l]);
        }
        if (base > 0)
            asm volatile("bar.sync %0, 64;" :: "r"(pair + 1) : "memory");
        if (half == 1) {
            // stage full t rows: lane l owns edge l (8 wide loads, high MLP)
            if (lane < rem) {
                const float4* tp = (const float4*)(g_t + e_l * H);
                float4 v0 = tp[0], v1 = tp[1], v2 = tp[2], v3 = tp[3];
                float4 v4 = tp[4], v5 = tp[5], v6 = tp[6], v7 = tp[7];
                float* dp = &t_st[pair][lane][0];
                *(float4*)(dp + 0)  = v0; *(float4*)(dp + 4)  = v1;
                *(float4*)(dp + 8)  = v2; *(float4*)(dp + 12) = v3;
                *(float4*)(dp + 16) = v4; *(float4*)(dp + 20) = v5;
                *(float4*)(dp + 24) = v6; *(float4*)(dp + 28) = v7;
            }
        } else {
            // stage h rows: 32 independent coalesced loads
            for (int p = 0; p < rem; p++) {
                int s = __shfl_sync(0xffffffffu, s_l, p);
                h_st[pair][p][lane] = h[s * H + lane];
            }
        }
        asm volatile("bar.sync %0, 64;" :: "r"(pair + 1) : "memory");
        // compute entirely from smem
        #pragma unroll 2
        for (int p = 0; p < rem; p++) {
            float hv = h_st[pair][p][lane];
            const float* tr = &t_st[pair][p][toff];
            ulonglong2 ua = *(const ulonglong2*)(tr + 0);
            ulonglong2 ub = *(const ulonglong2*)(tr + 4);
            ulonglong2 uc = *(const ulonglong2*)(tr + 8);
            ulonglong2 ud = *(const ulonglong2*)(tr + 12);
            hsum += hv;
            ull h2; PK2(h2, hv, hv);
            FMA2(acc2[0], ua.x, h2, acc2[0]);
            FMA2(acc2[1], ua.y, h2, acc2[1]);
            FMA2(acc2[2], ub.x, h2, acc2[2]);
            FMA2(acc2[3], ub.y, h2, acc2[3]);
            FMA2(acc2[4], uc.x, h2, acc2[4]);
            FMA2(acc2[5], uc.y, h2, acc2[5]);
            FMA2(acc2[6], ud.x, h2, acc2[6]);
            FMA2(acc2[7], ud.y, h2, acc2[7]);
        }
    }
    float* Pr = g_P + (long)d * KP;
    #pragma unroll
    for (int q = 0; q < 8; q++) {
        float x, y; UPK2(x, y, acc2[q]);
        Pr[(toff + 2 * q) * H + lane]     = x;
        Pr[(toff + 2 * q + 1) * H + lane] = y;
    }
    if (half == 0) Pr[1024 + lane] = hsum;
    else           Pr[1056 + lane] = 0.0f;
}

// -------- split-K GEMM --------
__device__ __forceinline__ void gemm_load(int kb, int tid, int nb,
                                          float4* va, float4& wb0, float4& wb1) {
    #pragma unroll
    for (int i = 0; i < 8; i++) {
        int idx = i * 288 + tid;
        int node = idx >> 4, q = idx & 15;
        int gn = nb + node;
        if (gn < NN) va[i] = *(const float4*)(g_P + (long)gn * KP + kb + 4 * q);
        else         va[i] = make_float4(0.f, 0.f, 0.f, 0.f);
    }
    {
        int r = tid >> 3, c = (tid & 7) * 4;
        wb0 = *(const float4*)(g_W2 + (kb + r) * H + c);
    }
    if (tid < 224) {
        int idx = tid + 288;
        int r = idx >> 3, c = (idx & 7) * 4;
        wb1 = *(const float4*)(g_W2 + (kb + r) * H + c);
    }
}

__global__ void __launch_bounds__(288) k_gemm() {
    __shared__ float AsT[64][160];
    __shared__ float Bs[64][32];
    int tid = threadIdx.x;
    int nb = blockIdx.x * BM;
    int split = blockIdx.y;
    int t0 = split ? 9 : 0;
    int nt = split ? 8 : 9;
    float* mo = split ? g_m2 : g_m;
    int tx = tid & 7, ty = tid >> 3;
    ull acc[4][2];
    #pragma unroll
    for (int n = 0; n < 4; n++) { acc[n][0] = 0ull; acc[n][1] = 0ull; }

    float4 va[8];
    float4 wb0 = make_float4(0.f, 0.f, 0.f, 0.f), wb1 = wb0;
    gemm_load(t0 * 64, tid, nb, va, wb0, wb1);

    #pragma unroll 1
    for (int t = 0; t < nt; t++) {
        __syncthreads();
        #pragma unroll
        for (int i = 0; i < 8; i++) {
            int idx = i * 288 + tid;
            int node = idx >> 4, q = idx & 15;
            int col = node ^ ((q & 7) << 2);
            AsT[4 * q + 0][col] = va[i].x;
            AsT[4 * q + 1][col] = va[i].y;
            AsT[4 * q + 2][col] = va[i].z;
            AsT[4 * q + 3][col] = va[i].w;
        }
        { int r = tid >> 3, c = (tid & 7) * 4; *(float4*)&Bs[r][c] = wb0; }
        if (tid < 224) { int idx = tid + 288; int r = idx >> 3, c = (idx & 7) * 4; *(float4*)&Bs[r][c] = wb1; }
        __syncthreads();
        if (t + 1 < nt) gemm_load((t0 + t + 1) * 64, tid, nb, va, wb0, wb1);
        #pragma unroll 16
        for (int kk = 0; kk < 64; kk++) {
            float4 a4 = *(const float4*)&AsT[kk][(4 * ty) ^ (((kk >> 2) & 7) << 2)];
            ulonglong2 b2 = *(const ulonglong2*)&Bs[kk][4 * tx];
            ull aa;
            PK2(aa, a4.x, a4.x); FMA2(acc[0][0], aa, b2.x, acc[0][0]); FMA2(acc[0][1], aa, b2.y, acc[0][1]);
            PK2(aa, a4.y, a4.y); FMA2(acc[1][0], aa, b2.x, acc[1][0]); FMA2(acc[1][1], aa, b2.y, acc[1][1]);
            PK2(aa, a4.z, a4.z); FMA2(acc[2][0], aa, b2.x, acc[2][0]); FMA2(acc[2][1], aa, b2.y, acc[2][1]);
            PK2(aa, a4.w, a4.w); FMA2(acc[3][0], aa, b2.x, acc[3][0]); FMA2(acc[3][1], aa, b2.y, acc[3][1]);
        }
    }
    #pragma unroll
    for (int n = 0; n < 4; n++) {
        int node = nb + 4 * ty + n;
        if (node < NN) {
            float x0, x1, x2, x3;
            UPK2(x0, x1, acc[n][0]);
            UPK2(x2, x3, acc[n][1]);
            *(float4*)(mo + node * H + 4 * tx) = make_float4(x0, x1, x2, x3);
        }
    }
}

__global__ void k_gru(int hin, int hout,
                      const float* __restrict__ Wih, const float* __restrict__ Whh,
                      const float* __restrict__ bih, const float* __restrict__ bhh) {
    __shared__ float Wis[96 * 33], Whs[96 * 33];
    __shared__ float bis[96], bhs[96];
    for (int i = threadIdx.x; i < 96 * 32; i += 256) {
        int r = i >> 5, cc = i & 31;
        Wis[r * 33 + cc] = Wih[i];
        Whs[r * 33 + cc] = Whh[i];
    }
    if (threadIdx.x < 96) { bis[threadIdx.x] = bih[threadIdx.x]; bhs[threadIdx.x] = bhh[threadIdx.x]; }
    __syncthreads();
    int n = blockIdx.x * 8 + (threadIdx.x >> 5);
    int c = threadIdx.x & 31;
    float mv = fmaxf((g_m[n * H + c] + g_m2[n * H + c]) * g_inv[n], 0.0f);
    float hv = g_h[hin][n * H + c];
    float gi0 = bis[c], gi1 = bis[c + 32], gi2 = bis[c + 64];
    float gh0 = bhs[c], gh1 = bhs[c + 32], gh2 = bhs[c + 64];
    #pragma unroll
    for (int j = 0; j < H; j++) {
        float mj = __shfl_sync(0xffffffffu, mv, j);
        float hj = __shfl_sync(0xffffffffu, hv, j);
        gi0 += mj * Wis[c * 33 + j];
        gi1 += mj * Wis[(c + 32) * 33 + j];
        gi2 += mj * Wis[(c + 64) * 33 + j];
        gh0 += hj * Whs[c * 33 + j];
        gh1 += hj * Whs[(c + 32) * 33 + j];
        gh2 += hj * Whs[(c + 64) * 33 + j];
    }
    float r = 1.0f / (1.0f + __expf(-(gi0 + gh0)));
    float z = 1.0f / (1.0f + __expf(-(gi1 + gh1)));
    float nn = tanhf(gi2 + r * gh2);
    g_h[hout][n * H + c] = (1.0f - z) * nn + z * hv;
}

__device__ __forceinline__ int lbound(const int* a, int n, int key) {
    int lo = 0, hi = n;
    while (lo < hi) { int mid = (lo + hi) >> 1; if (a[mid] < key) lo = mid + 1; else hi = mid; }
    return lo;
}

__global__ void k_readout(int hs, const int* __restrict__ gid, float* __restrict__ out) {
    __shared__ float red[4][32];
    int b = blockIdx.x;
    int lo = lbound(gid, NN, b), hi = lbound(gid, NN, b + 1);
    int w = threadIdx.x >> 5, lane = threadIdx.x & 31;
    const float* h = g_h[hs];
    float s = 0.0f;
    for (int n = lo + w; n < hi; n += 4) s += h[n * H + lane];
    red[w][lane] = s;
    __syncthreads();
    if (w == 0) {
        float tot = red[0][lane] + red[1][lane] + red[2][lane] + red[3][lane];
        out[b * H + lane] = tot / fmaxf((float)(hi - lo), 1.0f);
    }
}

extern "C" void kernel_launch(void* const* d_in, const int* in_sizes, int n_in,
                              void* d_out, int out_size) {
    const float* n_feat = (const float*)d_in[0];
    const float* e_feat = (const float*)d_in[1];
    const int*   src    = (const int*)d_in[2];
    const int*   dst    = (const int*)d_in[3];
    const int*   gid    = (const int*)d_in[4];
    float* out = (float*)d_out;

    k_prep<<<3887, 256>>>(dst, (const float*)d_in[7], (const float*)d_in[8],
                          (const float*)d_in[9], (const float*)d_in[10],
                          n_feat, (const float*)d_in[5], (const float*)d_in[6],
                          (const float*)d_in[11], (const float*)d_in[12]);
    k_scan<<<1, 1024>>>();
    k_scatter_t<<<2500, 256>>>(dst, e_feat);

    dim3 ggrid((NN + BM - 1) / BM, 2);
    for (int l = 0; l < 2; l++) {
        k_accum<<<NN / 4, 256>>>(l, l == 0 ? 1 : 0, src);   // 4th launch on l==0 -> profiled
        k_gemm<<<ggrid, 288>>>();
        k_gru<<<NN / 8, 256>>>(l, l + 1, (const float*)d_in[13], (const float*)d_in[14],
                               (const float*)d_in[15], (const float*)d_in[16]);
    }
    k_readout<<<NB, 128>>>(2, gid, out);
}